// round 15
// baseline (speedup 1.0000x reference)
#include <cuda_runtime.h>
#include <cstdint>

// ---------------------------------------------------------------- dims
#define BATCH 1024
#define HID   512
#define SRC   32
#define TT    32
#define VOC   256
#define EMB   256
#define GIN_K 768
#define G3H   1536
#define NBIG  2048         // Wa(512) + W_hh1(1536)
#define KQ    128          // K quarter
#define NSPLIT 4

#define OFF_DEC  0
#define OFF_ATT  (BATCH*TT)
#define OFF_LOSS (OFF_ATT + TT*BATCH*SRC)
#define OFF_COR  (OFF_LOSS + 1)

// ---------------------------------------------------------------- scratch
__device__ float g_kproj[SRC*BATCH*HID];
__device__ float g_Wbig[NBIG*HID];      // [Wa ; W_hh1]
__device__ float g_biasbig[NBIG];
__device__ float g_xrelu[VOC*EMB];
__device__ float g_EP[VOC*G3H];
__device__ float g_h0[BATCH*HID];
__device__ float g_h1[BATCH*HID];
__device__ float g_ctx[BATCH*HID];
__device__ float g_CbigP[NSPLIT][BATCH*NBIG];
__device__ float g_giP[NSPLIT][BATCH*G3H];
__device__ float g_ghP[NSPLIT][BATCH*G3H];
__device__ float g_logits[BATCH*VOC];
__device__ int   g_tok[BATCH];
__device__ float g_lossacc[BATCH];
__device__ int   g_match[BATCH];

// ---------------------------------------------------------------- 128x128 tile, 256 threads, 8x8/thread, double-buffered
// FFMA:LDS balanced 1:1. Per-element K order identical to prior rounds.
#define TM 128
#define TN 128
#define BK 16
__device__ __forceinline__ void gemm_tile(const float* __restrict__ A, int lda,
                                          const float* __restrict__ W, int ldb,
                                          const float* __restrict__ bias,
                                          const float* __restrict__ ep,
                                          const int* __restrict__ tok, int ldep,
                                          float* __restrict__ C, int ldc,
                                          int K, int bm, int bn) {
    __shared__ float As[2][BK][TM];
    __shared__ float Bs[2][BK][TN];
    const int tid = threadIdx.x;
    const int lr = tid >> 1;            // 0..127
    const int lc = (tid & 1) << 3;      // 0 or 8
    const int crow = (tid >> 4) << 3;   // 0..120
    const int ccol = (tid & 15) << 3;   // 0..120

    float acc[8][8];
#pragma unroll
    for (int i = 0; i < 8; ++i)
#pragma unroll
        for (int j = 0; j < 8; ++j) acc[i][j] = 0.f;

    const int nk = K / BK;
    {
        float4 a0 = *(const float4*)&A[(size_t)(bm + lr) * lda + lc];
        float4 a1 = *(const float4*)&A[(size_t)(bm + lr) * lda + lc + 4];
        float4 b0 = *(const float4*)&W[(size_t)(bn + lr) * ldb + lc];
        float4 b1 = *(const float4*)&W[(size_t)(bn + lr) * ldb + lc + 4];
        As[0][lc+0][lr] = a0.x; As[0][lc+1][lr] = a0.y; As[0][lc+2][lr] = a0.z; As[0][lc+3][lr] = a0.w;
        As[0][lc+4][lr] = a1.x; As[0][lc+5][lr] = a1.y; As[0][lc+6][lr] = a1.z; As[0][lc+7][lr] = a1.w;
        Bs[0][lc+0][lr] = b0.x; Bs[0][lc+1][lr] = b0.y; Bs[0][lc+2][lr] = b0.z; Bs[0][lc+3][lr] = b0.w;
        Bs[0][lc+4][lr] = b1.x; Bs[0][lc+5][lr] = b1.y; Bs[0][lc+6][lr] = b1.z; Bs[0][lc+7][lr] = b1.w;
    }
    __syncthreads();

    for (int kc = 0; kc < nk; ++kc) {
        const int cur = kc & 1;
        float4 na0, na1, nb0, nb1;
        const bool more = (kc + 1 < nk);
        if (more) {
            const int k0 = (kc + 1) * BK;
            na0 = *(const float4*)&A[(size_t)(bm + lr) * lda + k0 + lc];
            na1 = *(const float4*)&A[(size_t)(bm + lr) * lda + k0 + lc + 4];
            nb0 = *(const float4*)&W[(size_t)(bn + lr) * ldb + k0 + lc];
            nb1 = *(const float4*)&W[(size_t)(bn + lr) * ldb + k0 + lc + 4];
        }
#pragma unroll
        for (int kk = 0; kk < BK; ++kk) {
            float4 av0 = *(const float4*)&As[cur][kk][crow];
            float4 av1 = *(const float4*)&As[cur][kk][crow + 4];
            float4 bv0 = *(const float4*)&Bs[cur][kk][ccol];
            float4 bv1 = *(const float4*)&Bs[cur][kk][ccol + 4];
            float a[8] = {av0.x, av0.y, av0.z, av0.w, av1.x, av1.y, av1.z, av1.w};
            float b[8] = {bv0.x, bv0.y, bv0.z, bv0.w, bv1.x, bv1.y, bv1.z, bv1.w};
#pragma unroll
            for (int i = 0; i < 8; ++i)
#pragma unroll
                for (int j = 0; j < 8; ++j) acc[i][j] += a[i] * b[j];
        }
        if (more) {
            const int nxt = 1 - cur;
            As[nxt][lc+0][lr] = na0.x; As[nxt][lc+1][lr] = na0.y; As[nxt][lc+2][lr] = na0.z; As[nxt][lc+3][lr] = na0.w;
            As[nxt][lc+4][lr] = na1.x; As[nxt][lc+5][lr] = na1.y; As[nxt][lc+6][lr] = na1.z; As[nxt][lc+7][lr] = na1.w;
            Bs[nxt][lc+0][lr] = nb0.x; Bs[nxt][lc+1][lr] = nb0.y; Bs[nxt][lc+2][lr] = nb0.z; Bs[nxt][lc+3][lr] = nb0.w;
            Bs[nxt][lc+4][lr] = nb1.x; Bs[nxt][lc+5][lr] = nb1.y; Bs[nxt][lc+6][lr] = nb1.z; Bs[nxt][lc+7][lr] = nb1.w;
        }
        __syncthreads();
    }

    float4 bvlo = bias ? *(const float4*)&bias[bn + ccol] : make_float4(0.f, 0.f, 0.f, 0.f);
    float4 bvhi = bias ? *(const float4*)&bias[bn + ccol + 4] : make_float4(0.f, 0.f, 0.f, 0.f);
#pragma unroll
    for (int i = 0; i < 8; ++i) {
        const int row = bm + crow + i;
        float4 r0, r1;
        r0.x = acc[i][0] + bvlo.x; r0.y = acc[i][1] + bvlo.y;
        r0.z = acc[i][2] + bvlo.z; r0.w = acc[i][3] + bvlo.w;
        r1.x = acc[i][4] + bvhi.x; r1.y = acc[i][5] + bvhi.y;
        r1.z = acc[i][6] + bvhi.z; r1.w = acc[i][7] + bvhi.w;
        if (ep) {
            const float* eprow = &ep[(size_t)tok[row] * ldep + bn + ccol];
            const float4 e0 = *(const float4*)eprow;
            const float4 e1 = *(const float4*)(eprow + 4);
            r0.x += e0.x; r0.y += e0.y; r0.z += e0.z; r0.w += e0.w;
            r1.x += e1.x; r1.y += e1.y; r1.z += e1.z; r1.w += e1.w;
        }
        *(float4*)&C[(size_t)row * ldc + bn + ccol] = r0;
        *(float4*)&C[(size_t)row * ldc + bn + ccol + 4] = r1;
    }
}

// ---------------------------------------------------------------- GEMM wrappers
__global__ void __launch_bounds__(256) k_kproj(const float* __restrict__ enc,
                                               const float* __restrict__ Ua,
                                               const float* __restrict__ bUa) {
    gemm_tile(enc, HID, Ua, HID, bUa, nullptr, nullptr, 0,
              g_kproj, HID, HID, blockIdx.y * TM, blockIdx.x * TN);
}

__global__ void __launch_bounds__(256) k_ep(const float* __restrict__ W_ih0) {
    gemm_tile(g_xrelu, EMB, W_ih0, GIN_K, nullptr, nullptr, nullptr, 0,
              g_EP, G3H, EMB, blockIdx.y * TM, blockIdx.x * TN);
}

// z = (kq<<1)|which: which 0 -> Cbig partial, 1 -> gh partial
__global__ void __launch_bounds__(256) k_dual(const float* __restrict__ Whh0,
                                              const float* __restrict__ b_hh0) {
    const int which = blockIdx.z & 1;
    const int kq = blockIdx.z >> 1;
    const int koff = kq * KQ;
    if (which == 0) {
        gemm_tile(g_h1 + koff, HID, g_Wbig + koff, HID,
                  kq == 0 ? g_biasbig : nullptr, nullptr, nullptr, 0,
                  g_CbigP[kq], NBIG, KQ, blockIdx.y * TM, blockIdx.x * TN);
    } else {
        if (blockIdx.x >= G3H / TN) return;
        gemm_tile(g_h0 + koff, HID, Whh0 + koff, HID,
                  kq == 0 ? b_hh0 : nullptr, nullptr, nullptr, 0,
                  g_ghP[kq], G3H, KQ, blockIdx.y * TM, blockIdx.x * TN);
    }
}

__global__ void __launch_bounds__(256) k_gi0(const float* __restrict__ W_ih0,
                                             const float* __restrict__ b_ih0) {
    const int kq = blockIdx.z;
    const int koff = kq * KQ;
    gemm_tile(g_ctx + koff, HID, W_ih0 + EMB + koff, GIN_K,
              kq == 0 ? b_ih0 : nullptr,
              kq == 0 ? g_EP : nullptr, g_tok, G3H,
              g_giP[kq], G3H, KQ, blockIdx.y * TM, blockIdx.x * TN);
}

__global__ void __launch_bounds__(256) k_gi1(const float* __restrict__ W_ih1,
                                             const float* __restrict__ b_ih1) {
    const int kq = blockIdx.z;
    const int koff = kq * KQ;
    gemm_tile(g_h0 + koff, HID, W_ih1 + koff, HID,
              kq == 0 ? b_ih1 : nullptr, nullptr, nullptr, 0,
              g_giP[kq], G3H, KQ, blockIdx.y * TM, blockIdx.x * TN);
}

// ---------------------------------------------------------------- logits GEMM (r12-proven 64x32)
#define LBM 64
#define LBN 32
__global__ void __launch_bounds__(128) k_logits(const float* __restrict__ fcW,
                                                const float* __restrict__ fcb) {
    __shared__ float As[BK][LBM];
    __shared__ float Bs[BK][LBN];
    const int tid = threadIdx.x;
    const int bm = blockIdx.y * LBM;
    const int bn = blockIdx.x * LBN;

    const int lrA = tid >> 1;
    const int lcA = (tid & 1) << 3;
    const int lrB = tid >> 2;
    const int lcB = (tid & 3) << 2;
    const int crow = (tid >> 3) << 2;
    const int ccol = (tid & 7) << 2;

    float acc[4][4];
#pragma unroll
    for (int i = 0; i < 4; ++i)
#pragma unroll
        for (int j = 0; j < 4; ++j) acc[i][j] = 0.f;

    for (int k0 = 0; k0 < HID; k0 += BK) {
        float4 a0 = *(const float4*)&g_h1[(size_t)(bm + lrA) * HID + k0 + lcA];
        float4 a1 = *(const float4*)&g_h1[(size_t)(bm + lrA) * HID + k0 + lcA + 4];
        float4 b0 = *(const float4*)&fcW[(size_t)(bn + lrB) * HID + k0 + lcB];
        As[lcA+0][lrA] = a0.x; As[lcA+1][lrA] = a0.y; As[lcA+2][lrA] = a0.z; As[lcA+3][lrA] = a0.w;
        As[lcA+4][lrA] = a1.x; As[lcA+5][lrA] = a1.y; As[lcA+6][lrA] = a1.z; As[lcA+7][lrA] = a1.w;
        Bs[lcB+0][lrB] = b0.x; Bs[lcB+1][lrB] = b0.y; Bs[lcB+2][lrB] = b0.z; Bs[lcB+3][lrB] = b0.w;
        __syncthreads();
#pragma unroll
        for (int kk = 0; kk < BK; ++kk) {
            float4 av = *(const float4*)&As[kk][crow];
            float4 bv = *(const float4*)&Bs[kk][ccol];
            float a[4] = {av.x, av.y, av.z, av.w};
            float b[4] = {bv.x, bv.y, bv.z, bv.w};
#pragma unroll
            for (int i = 0; i < 4; ++i)
#pragma unroll
                for (int j = 0; j < 4; ++j) acc[i][j] += a[i] * b[j];
        }
        __syncthreads();
    }

    const float4 bv = *(const float4*)&fcb[bn + ccol];
#pragma unroll
    for (int i = 0; i < 4; ++i) {
        float4 r;
        r.x = acc[i][0] + bv.x; r.y = acc[i][1] + bv.y;
        r.z = acc[i][2] + bv.z; r.w = acc[i][3] + bv.w;
        *(float4*)&g_logits[(size_t)(bm + crow + i) * VOC + bn + ccol] = r;
    }
}

// ---------------------------------------------------------------- aux kernels
__global__ void wcat_kernel(const float* __restrict__ Wa, const float* __restrict__ Whh1,
                            const float* __restrict__ bWa, const float* __restrict__ bhh1,
                            const float* __restrict__ emb) {
    int i = blockIdx.x * blockDim.x + threadIdx.x;
    int row = i >> 9, col = i & 511;
    g_Wbig[i] = (row < HID) ? Wa[row * HID + col] : Whh1[(row - HID) * HID + col];
    if (i < HID) g_biasbig[i] = bWa[i];
    else if (i < NBIG) g_biasbig[i] = bhh1[i - HID];
    if (i < VOC * EMB) {
        float v = emb[i];
        g_xrelu[i] = v > 0.f ? v : 0.f;
    }
}

__global__ void init_kernel(const float* __restrict__ state) {
    int idx = blockIdx.x * blockDim.x + threadIdx.x;
    if (idx < BATCH * HID) {
        g_h0[idx] = state[idx];
        g_h1[idx] = state[BATCH * HID + idx];
    }
    if (idx < BATCH) { g_tok[idx] = 1; g_lossacc[idx] = 0.f; g_match[idx] = 1; }
}

__global__ void __launch_bounds__(256) attn_kernel(const float* __restrict__ enc,
                                                   const float* __restrict__ Va,
                                                   const float* __restrict__ bVa,
                                                   float* __restrict__ out_attn, int t) {
    int b = blockIdx.x;
    int warp = threadIdx.x >> 5, lane = threadIdx.x & 31;
    __shared__ float e_sh[SRC];
    __shared__ float w_sh[SRC];

    float part[4] = {0.f, 0.f, 0.f, 0.f};
    for (int h = lane; h < HID; h += 32) {
        const size_t o = (size_t)b * NBIG + h;
        float q = g_CbigP[0][o] + g_CbigP[1][o] + g_CbigP[2][o] + g_CbigP[3][o];
        float va = Va[h];
#pragma unroll
        for (int i = 0; i < 4; ++i) {
            int s = warp * 4 + i;
            part[i] += va * tanhf(q + g_kproj[((size_t)s * BATCH + b) * HID + h]);
        }
    }
#pragma unroll
    for (int i = 0; i < 4; ++i) {
#pragma unroll
        for (int o = 16; o > 0; o >>= 1) part[i] += __shfl_xor_sync(0xffffffffu, part[i], o);
        if (lane == 0) e_sh[warp * 4 + i] = part[i] + bVa[0];
    }
    __syncthreads();
    if (threadIdx.x < 32) {
        float x = e_sh[lane], m = x;
#pragma unroll
        for (int o = 16; o > 0; o >>= 1) m = fmaxf(m, __shfl_xor_sync(0xffffffffu, m, o));
        float ex = expf(x - m), s = ex;
#pragma unroll
        for (int o = 16; o > 0; o >>= 1) s += __shfl_xor_sync(0xffffffffu, s, o);
        float w = ex / s;
        w_sh[lane] = w;
        out_attn[((size_t)t * BATCH + b) * SRC + lane] = w;
    }
    __syncthreads();
    for (int h = threadIdx.x; h < HID; h += 256) {
        float c = 0.f;
#pragma unroll
        for (int s = 0; s < SRC; ++s) c += w_sh[s] * enc[((size_t)s * BATCH + b) * HID + h];
        g_ctx[b * HID + h] = c;
    }
}

__device__ __forceinline__ float sigmf(float x) { return 1.f / (1.f + expf(-x)); }

__global__ void gru_pw0() {
    int idx = blockIdx.x * blockDim.x + threadIdx.x;
    int b = idx >> 9, j = idx & 511;
    const size_t o = (size_t)b * G3H;
    float gr = g_giP[0][o + j] + g_giP[1][o + j] + g_giP[2][o + j] + g_giP[3][o + j];
    float gz = g_giP[0][o + HID + j] + g_giP[1][o + HID + j] + g_giP[2][o + HID + j] + g_giP[3][o + HID + j];
    float gn = g_giP[0][o + 2*HID + j] + g_giP[1][o + 2*HID + j] + g_giP[2][o + 2*HID + j] + g_giP[3][o + 2*HID + j];
    float hr = g_ghP[0][o + j] + g_ghP[1][o + j] + g_ghP[2][o + j] + g_ghP[3][o + j];
    float hz = g_ghP[0][o + HID + j] + g_ghP[1][o + HID + j] + g_ghP[2][o + HID + j] + g_ghP[3][o + HID + j];
    float hn = g_ghP[0][o + 2*HID + j] + g_ghP[1][o + 2*HID + j] + g_ghP[2][o + 2*HID + j] + g_ghP[3][o + 2*HID + j];
    float r = sigmf(gr + hr);
    float z = sigmf(gz + hz);
    float n = tanhf(gn + r * hn);
    float hp = g_h0[idx];
    g_h0[idx] = (1.f - z) * n + z * hp;
}

__global__ void gru_pw1() {
    int idx = blockIdx.x * blockDim.x + threadIdx.x;
    int b = idx >> 9, j = idx & 511;
    const size_t o = (size_t)b * G3H;
    const size_t oc = (size_t)b * NBIG + HID;
    float gr = g_giP[0][o + j] + g_giP[1][o + j] + g_giP[2][o + j] + g_giP[3][o + j];
    float gz = g_giP[0][o + HID + j] + g_giP[1][o + HID + j] + g_giP[2][o + HID + j] + g_giP[3][o + HID + j];
    float gn = g_giP[0][o + 2*HID + j] + g_giP[1][o + 2*HID + j] + g_giP[2][o + 2*HID + j] + g_giP[3][o + 2*HID + j];
    float hr = g_CbigP[0][oc + j] + g_CbigP[1][oc + j] + g_CbigP[2][oc + j] + g_CbigP[3][oc + j];
    float hz = g_CbigP[0][oc + HID + j] + g_CbigP[1][oc + HID + j] + g_CbigP[2][oc + HID + j] + g_CbigP[3][oc + HID + j];
    float hn = g_CbigP[0][oc + 2*HID + j] + g_CbigP[1][oc + 2*HID + j] + g_CbigP[2][oc + 2*HID + j] + g_CbigP[3][oc + 2*HID + j];
    float r = sigmf(gr + hr);
    float z = sigmf(gz + hz);
    float n = tanhf(gn + r * hn);
    float hp = g_h1[idx];
    g_h1[idx] = (1.f - z) * n + z * hp;
}

__global__ void __launch_bounds__(256) fc_finalize(const int* __restrict__ target,
                                                   float* __restrict__ out_dec, int t) {
    int b = blockIdx.x;
    int v = threadIdx.x;
    float lg = g_logits[b * VOC + v];
    __shared__ float sval[VOC];
    __shared__ int sidx[VOC];
    sval[v] = lg; sidx[v] = v;
    __syncthreads();
    for (int off = 128; off > 0; off >>= 1) {
        if (v < off) {
            float ov = sval[v + off]; int oi = sidx[v + off];
            if (ov > sval[v] || (ov == sval[v] && oi < sidx[v])) { sval[v] = ov; sidx[v] = oi; }
        }
        __syncthreads();
    }
    float m = sval[0]; int am = sidx[0];
    __syncthreads();
    sval[v] = expf(lg - m);
    __syncthreads();
    for (int off = 128; off > 0; off >>= 1) {
        if (v < off) sval[v] += sval[v + off];
        __syncthreads();
    }
    if (v == 0) {
        float lse = m + logf(sval[0]);
        int tgt = target[b * TT + t];
        g_lossacc[b] += lse - g_logits[b * VOC + tgt];
        if (am != tgt) g_match[b] = 0;
        g_tok[b] = am;
        out_dec[b * TT + t] = (float)am;
    }
}

__global__ void __launch_bounds__(256) final_reduce(float* __restrict__ out) {
    __shared__ float sl[256];
    __shared__ int sc[256];
    float l = 0.f; int c = 0;
    for (int b = threadIdx.x; b < BATCH; b += 256) { l += g_lossacc[b]; c += g_match[b]; }
    sl[threadIdx.x] = l; sc[threadIdx.x] = c;
    __syncthreads();
    for (int off = 128; off > 0; off >>= 1) {
        if (threadIdx.x < off) { sl[threadIdx.x] += sl[threadIdx.x + off]; sc[threadIdx.x] += sc[threadIdx.x + off]; }
        __syncthreads();
    }
    if (threadIdx.x == 0) {
        out[OFF_LOSS] = sl[0] / (float)BATCH;
        out[OFF_COR] = (float)sc[0];
    }
}

// ---------------------------------------------------------------- launch
extern "C" void kernel_launch(void* const* d_in, const int* in_sizes, int n_in,
                              void* d_out, int out_size) {
    const float* state = (const float*)d_in[0];
    const float* enc   = (const float*)d_in[1];
    const int*   tgt   = (const int*)d_in[2];
    const float* emb   = (const float*)d_in[3];
    const float* Wa    = (const float*)d_in[4];
    const float* bWa   = (const float*)d_in[5];
    const float* Ua    = (const float*)d_in[6];
    const float* bUa   = (const float*)d_in[7];
    const float* Va    = (const float*)d_in[8];
    const float* bVa   = (const float*)d_in[9];
    const float* W_ih0 = (const float*)d_in[10];
    const float* W_hh0 = (const float*)d_in[11];
    const float* b_ih0 = (const float*)d_in[12];
    const float* b_hh0 = (const float*)d_in[13];
    const float* W_ih1 = (const float*)d_in[14];
    const float* W_hh1 = (const float*)d_in[15];
    const float* b_ih1 = (const float*)d_in[16];
    const float* b_hh1 = (const float*)d_in[17];
    const float* fcW   = (const float*)d_in[18];
    const float* fcb   = (const float*)d_in[19];
    float* out = (float*)d_out;

    // ---- init + weight prep ----
    init_kernel<<<(BATCH * HID + 255) / 256, 256>>>(state);
    wcat_kernel<<<(NBIG * HID + 255) / 256, 256>>>(Wa, W_hh1, bWa, b_hh1, emb);

    // kproj (M=32768, N=512): 256x4 = 1024 blocks
    k_kproj<<<dim3(HID / TN, (SRC * BATCH) / TM), 256>>>(enc, Ua, bUa);
    // EP (M=256, N=1536): 2x12 = 24 blocks
    k_ep<<<dim3(G3H / TN, VOC / TM), 256>>>(W_ih0);

    for (int t = 0; t < TT; ++t) {
        // dual K-split x4: z=(kq<<1)|which, 8 planes; 896 active blocks
        k_dual<<<dim3(NBIG / TN, BATCH / TM, 2 * NSPLIT), 256>>>(W_hh0, b_hh0);
        attn_kernel<<<BATCH, 256>>>(enc, Va, bVa, out + OFF_ATT, t);
        // gi0 partials: 12x8x4 = 384 blocks
        k_gi0<<<dim3(G3H / TN, BATCH / TM, NSPLIT), 256>>>(W_ih0, b_ih0);
        gru_pw0<<<(BATCH * HID) / 256, 256>>>();
        // gi1 partials: 384 blocks
        k_gi1<<<dim3(G3H / TN, BATCH / TM, NSPLIT), 256>>>(W_ih1, b_ih1);
        gru_pw1<<<(BATCH * HID) / 256, 256>>>();
        // logits
        k_logits<<<dim3(VOC / LBN, BATCH / LBM), 128>>>(fcW, fcb);
        fc_finalize<<<BATCH, 256>>>(tgt, out + OFF_DEC, t);
    }

    final_reduce<<<1, 256>>>(out);
}

// round 16
// speedup vs baseline: 1.0241x; 1.0241x over previous
#include <cuda_runtime.h>
#include <cstdint>

// ---------------------------------------------------------------- dims
#define BATCH 1024
#define HID   512
#define SRC   32
#define TT    32
#define VOC   256
#define EMB   256
#define GIN_K 768
#define G3H   1536
#define NBIG  2048         // Wa(512) + W_hh1(1536)
#define KQ    128          // K quarter
#define NSPLIT 4

#define OFF_DEC  0
#define OFF_ATT  (BATCH*TT)
#define OFF_LOSS (OFF_ATT + TT*BATCH*SRC)
#define OFF_COR  (OFF_LOSS + 1)

// ---------------------------------------------------------------- scratch
__device__ float g_kproj[SRC*BATCH*HID];
__device__ float g_Wbig[NBIG*HID];      // [Wa ; W_hh1]
__device__ float g_biasbig[NBIG];
__device__ float g_xrelu[VOC*EMB];
__device__ float g_EP[VOC*G3H];
__device__ float g_h0[BATCH*HID];
__device__ float g_h1[BATCH*HID];
__device__ float g_ctx[BATCH*HID];
__device__ float g_CbigP[NSPLIT][BATCH*NBIG];
__device__ float g_giP[NSPLIT][BATCH*G3H];
__device__ float g_ghP[NSPLIT][BATCH*G3H];
__device__ float g_logits[BATCH*VOC];
__device__ int   g_tok[BATCH];
__device__ float g_lossacc[BATCH];
__device__ int   g_match[BATCH];

// ---------------------------------------------------------------- 128x128 tile, 256 threads, 8x8/thread, double-buffered
#define TM 128
#define TN 128
#define BK 16
__device__ __forceinline__ void gemm_tile(const float* __restrict__ A, int lda,
                                          const float* __restrict__ W, int ldb,
                                          const float* __restrict__ bias,
                                          const float* __restrict__ ep,
                                          const int* __restrict__ tok, int ldep,
                                          float* __restrict__ C, int ldc,
                                          int K, int bm, int bn) {
    __shared__ float As[2][BK][TM];
    __shared__ float Bs[2][BK][TN];
    const int tid = threadIdx.x;
    const int lr = tid >> 1;            // 0..127
    const int lc = (tid & 1) << 3;      // 0 or 8
    const int crow = (tid >> 4) << 3;   // 0..120
    const int ccol = (tid & 15) << 3;   // 0..120

    float acc[8][8];
#pragma unroll
    for (int i = 0; i < 8; ++i)
#pragma unroll
        for (int j = 0; j < 8; ++j) acc[i][j] = 0.f;

    const int nk = K / BK;
    {
        float4 a0 = *(const float4*)&A[(size_t)(bm + lr) * lda + lc];
        float4 a1 = *(const float4*)&A[(size_t)(bm + lr) * lda + lc + 4];
        float4 b0 = *(const float4*)&W[(size_t)(bn + lr) * ldb + lc];
        float4 b1 = *(const float4*)&W[(size_t)(bn + lr) * ldb + lc + 4];
        As[0][lc+0][lr] = a0.x; As[0][lc+1][lr] = a0.y; As[0][lc+2][lr] = a0.z; As[0][lc+3][lr] = a0.w;
        As[0][lc+4][lr] = a1.x; As[0][lc+5][lr] = a1.y; As[0][lc+6][lr] = a1.z; As[0][lc+7][lr] = a1.w;
        Bs[0][lc+0][lr] = b0.x; Bs[0][lc+1][lr] = b0.y; Bs[0][lc+2][lr] = b0.z; Bs[0][lc+3][lr] = b0.w;
        Bs[0][lc+4][lr] = b1.x; Bs[0][lc+5][lr] = b1.y; Bs[0][lc+6][lr] = b1.z; Bs[0][lc+7][lr] = b1.w;
    }
    __syncthreads();

    for (int kc = 0; kc < nk; ++kc) {
        const int cur = kc & 1;
        float4 na0, na1, nb0, nb1;
        const bool more = (kc + 1 < nk);
        if (more) {
            const int k0 = (kc + 1) * BK;
            na0 = *(const float4*)&A[(size_t)(bm + lr) * lda + k0 + lc];
            na1 = *(const float4*)&A[(size_t)(bm + lr) * lda + k0 + lc + 4];
            nb0 = *(const float4*)&W[(size_t)(bn + lr) * ldb + k0 + lc];
            nb1 = *(const float4*)&W[(size_t)(bn + lr) * ldb + k0 + lc + 4];
        }
#pragma unroll
        for (int kk = 0; kk < BK; ++kk) {
            float4 av0 = *(const float4*)&As[cur][kk][crow];
            float4 av1 = *(const float4*)&As[cur][kk][crow + 4];
            float4 bv0 = *(const float4*)&Bs[cur][kk][ccol];
            float4 bv1 = *(const float4*)&Bs[cur][kk][ccol + 4];
            float a[8] = {av0.x, av0.y, av0.z, av0.w, av1.x, av1.y, av1.z, av1.w};
            float b[8] = {bv0.x, bv0.y, bv0.z, bv0.w, bv1.x, bv1.y, bv1.z, bv1.w};
#pragma unroll
            for (int i = 0; i < 8; ++i)
#pragma unroll
                for (int j = 0; j < 8; ++j) acc[i][j] += a[i] * b[j];
        }
        if (more) {
            const int nxt = 1 - cur;
            As[nxt][lc+0][lr] = na0.x; As[nxt][lc+1][lr] = na0.y; As[nxt][lc+2][lr] = na0.z; As[nxt][lc+3][lr] = na0.w;
            As[nxt][lc+4][lr] = na1.x; As[nxt][lc+5][lr] = na1.y; As[nxt][lc+6][lr] = na1.z; As[nxt][lc+7][lr] = na1.w;
            Bs[nxt][lc+0][lr] = nb0.x; Bs[nxt][lc+1][lr] = nb0.y; Bs[nxt][lc+2][lr] = nb0.z; Bs[nxt][lc+3][lr] = nb0.w;
            Bs[nxt][lc+4][lr] = nb1.x; Bs[nxt][lc+5][lr] = nb1.y; Bs[nxt][lc+6][lr] = nb1.z; Bs[nxt][lc+7][lr] = nb1.w;
        }
        __syncthreads();
    }

    float4 bvlo = bias ? *(const float4*)&bias[bn + ccol] : make_float4(0.f, 0.f, 0.f, 0.f);
    float4 bvhi = bias ? *(const float4*)&bias[bn + ccol + 4] : make_float4(0.f, 0.f, 0.f, 0.f);
#pragma unroll
    for (int i = 0; i < 8; ++i) {
        const int row = bm + crow + i;
        float4 r0, r1;
        r0.x = acc[i][0] + bvlo.x; r0.y = acc[i][1] + bvlo.y;
        r0.z = acc[i][2] + bvlo.z; r0.w = acc[i][3] + bvlo.w;
        r1.x = acc[i][4] + bvhi.x; r1.y = acc[i][5] + bvhi.y;
        r1.z = acc[i][6] + bvhi.z; r1.w = acc[i][7] + bvhi.w;
        if (ep) {
            const float* eprow = &ep[(size_t)tok[row] * ldep + bn + ccol];
            const float4 e0 = *(const float4*)eprow;
            const float4 e1 = *(const float4*)(eprow + 4);
            r0.x += e0.x; r0.y += e0.y; r0.z += e0.z; r0.w += e0.w;
            r1.x += e1.x; r1.y += e1.y; r1.z += e1.z; r1.w += e1.w;
        }
        *(float4*)&C[(size_t)row * ldc + bn + ccol] = r0;
        *(float4*)&C[(size_t)row * ldc + bn + ccol + 4] = r1;
    }
}

// ---------------------------------------------------------------- logits 64x32 tile, 256 threads (bit-identical K order)
#define LBM 64
#define LBN 32
__device__ __forceinline__ void logits_tile256(const float* __restrict__ fcW,
                                               const float* __restrict__ fcb,
                                               int flat) {
    __shared__ float As[BK][LBM];
    __shared__ float Bs[BK][LBN];
    const int tid = threadIdx.x;
    const int bn = (flat & 7) * LBN;     // 8 col tiles
    const int bm = (flat >> 3) * LBM;    // 16 row tiles

    const int lrA = tid >> 2;            // 0..63
    const int lcA = (tid & 3) << 2;      // 0,4,8,12
    const int lrB = tid >> 3;            // 0..31
    const int lcB = (tid & 7) << 1;      // 0..14
    const int crow = (tid >> 3) << 1;    // 0..62
    const int ccol = (tid & 7) << 2;     // 0..28

    float acc[2][4];
#pragma unroll
    for (int i = 0; i < 2; ++i)
#pragma unroll
        for (int j = 0; j < 4; ++j) acc[i][j] = 0.f;

    for (int k0 = 0; k0 < HID; k0 += BK) {
        float4 a0 = *(const float4*)&g_h1[(size_t)(bm + lrA) * HID + k0 + lcA];
        float2 b0 = *(const float2*)&fcW[(size_t)(bn + lrB) * HID + k0 + lcB];
        As[lcA+0][lrA] = a0.x; As[lcA+1][lrA] = a0.y; As[lcA+2][lrA] = a0.z; As[lcA+3][lrA] = a0.w;
        Bs[lcB+0][lrB] = b0.x; Bs[lcB+1][lrB] = b0.y;
        __syncthreads();
#pragma unroll
        for (int kk = 0; kk < BK; ++kk) {
            float a0v = As[kk][crow];
            float a1v = As[kk][crow + 1];
            float4 bv = *(const float4*)&Bs[kk][ccol];
            float b[4] = {bv.x, bv.y, bv.z, bv.w};
#pragma unroll
            for (int j = 0; j < 4; ++j) {
                acc[0][j] += a0v * b[j];
                acc[1][j] += a1v * b[j];
            }
        }
        __syncthreads();
    }

    const float4 bv = *(const float4*)&fcb[bn + ccol];
#pragma unroll
    for (int i = 0; i < 2; ++i) {
        float4 r;
        r.x = acc[i][0] + bv.x; r.y = acc[i][1] + bv.y;
        r.z = acc[i][2] + bv.z; r.w = acc[i][3] + bv.w;
        *(float4*)&g_logits[(size_t)(bm + crow + i) * VOC + bn + ccol] = r;
    }
}

// ---------------------------------------------------------------- fc finalize body (argmax, loss, token feedback)
__device__ __forceinline__ void finalize_body(const int* __restrict__ target,
                                              float* __restrict__ out_dec, int t, int b) {
    int v = threadIdx.x;
    float lg = g_logits[b * VOC + v];
    __shared__ float sval[VOC];
    __shared__ int sidx[VOC];
    sval[v] = lg; sidx[v] = v;
    __syncthreads();
    for (int off = 128; off > 0; off >>= 1) {
        if (v < off) {
            float ov = sval[v + off]; int oi = sidx[v + off];
            if (ov > sval[v] || (ov == sval[v] && oi < sidx[v])) { sval[v] = ov; sidx[v] = oi; }
        }
        __syncthreads();
    }
    float m = sval[0]; int am = sidx[0];
    __syncthreads();
    sval[v] = expf(lg - m);
    __syncthreads();
    for (int off = 128; off > 0; off >>= 1) {
        if (v < off) sval[v] += sval[v + off];
        __syncthreads();
    }
    if (v == 0) {
        float lse = m + logf(sval[0]);
        int tgt = target[b * TT + t];
        g_lossacc[b] += lse - g_logits[b * VOC + tgt];
        if (am != tgt) g_match[b] = 0;
        g_tok[b] = am;
        out_dec[b * TT + t] = (float)am;
    }
}

// ---------------------------------------------------------------- GEMM wrappers
__global__ void __launch_bounds__(256) k_kproj(const float* __restrict__ enc,
                                               const float* __restrict__ Ua,
                                               const float* __restrict__ bUa) {
    gemm_tile(enc, HID, Ua, HID, bUa, nullptr, nullptr, 0,
              g_kproj, HID, HID, blockIdx.y * TM, blockIdx.x * TN);
}

__global__ void __launch_bounds__(256) k_ep(const float* __restrict__ W_ih0) {
    gemm_tile(g_xrelu, EMB, W_ih0, GIN_K, nullptr, nullptr, nullptr, 0,
              g_EP, G3H, EMB, blockIdx.y * TM, blockIdx.x * TN);
}

// z<8: (kq<<1)|which dual planes; z==8: logits(t-1) plane (128 blocks)
__global__ void __launch_bounds__(256) k_dual(const float* __restrict__ Whh0,
                                              const float* __restrict__ b_hh0,
                                              const float* __restrict__ fcW,
                                              const float* __restrict__ fcb,
                                              int do_logits) {
    if (blockIdx.z == 2 * NSPLIT) {
        if (!do_logits) return;
        logits_tile256(fcW, fcb, blockIdx.y * 16 + blockIdx.x);
        return;
    }
    const int which = blockIdx.z & 1;
    const int kq = blockIdx.z >> 1;
    const int koff = kq * KQ;
    if (which == 0) {
        gemm_tile(g_h1 + koff, HID, g_Wbig + koff, HID,
                  kq == 0 ? g_biasbig : nullptr, nullptr, nullptr, 0,
                  g_CbigP[kq], NBIG, KQ, blockIdx.y * TM, blockIdx.x * TN);
    } else {
        if (blockIdx.x >= G3H / TN) return;
        gemm_tile(g_h0 + koff, HID, Whh0 + koff, HID,
                  kq == 0 ? b_hh0 : nullptr, nullptr, nullptr, 0,
                  g_ghP[kq], G3H, KQ, blockIdx.y * TM, blockIdx.x * TN);
    }
}

__global__ void __launch_bounds__(256) k_gi0(const float* __restrict__ W_ih0,
                                             const float* __restrict__ b_ih0) {
    const int kq = blockIdx.z;
    const int koff = kq * KQ;
    gemm_tile(g_ctx + koff, HID, W_ih0 + EMB + koff, GIN_K,
              kq == 0 ? b_ih0 : nullptr,
              kq == 0 ? g_EP : nullptr, g_tok, G3H,
              g_giP[kq], G3H, KQ, blockIdx.y * TM, blockIdx.x * TN);
}

__global__ void __launch_bounds__(256) k_gi1(const float* __restrict__ W_ih1,
                                             const float* __restrict__ b_ih1) {
    const int kq = blockIdx.z;
    const int koff = kq * KQ;
    gemm_tile(g_h0 + koff, HID, W_ih1 + koff, HID,
              kq == 0 ? b_ih1 : nullptr, nullptr, nullptr, 0,
              g_giP[kq], G3H, KQ, blockIdx.y * TM, blockIdx.x * TN);
}

// tail logits (t=31)
__global__ void __launch_bounds__(256) k_logits_tail(const float* __restrict__ fcW,
                                                     const float* __restrict__ fcb) {
    logits_tile256(fcW, fcb, blockIdx.x);
}

__global__ void __launch_bounds__(256) fc_finalize(const int* __restrict__ target,
                                                   float* __restrict__ out_dec, int t) {
    finalize_body(target, out_dec, t, blockIdx.x);
}

// ---------------------------------------------------------------- aux kernels
__global__ void wcat_kernel(const float* __restrict__ Wa, const float* __restrict__ Whh1,
                            const float* __restrict__ bWa, const float* __restrict__ bhh1,
                            const float* __restrict__ emb) {
    int i = blockIdx.x * blockDim.x + threadIdx.x;
    int row = i >> 9, col = i & 511;
    g_Wbig[i] = (row < HID) ? Wa[row * HID + col] : Whh1[(row - HID) * HID + col];
    if (i < HID) g_biasbig[i] = bWa[i];
    else if (i < NBIG) g_biasbig[i] = bhh1[i - HID];
    if (i < VOC * EMB) {
        float v = emb[i];
        g_xrelu[i] = v > 0.f ? v : 0.f;
    }
}

__global__ void init_kernel(const float* __restrict__ state) {
    int idx = blockIdx.x * blockDim.x + threadIdx.x;
    if (idx < BATCH * HID) {
        g_h0[idx] = state[idx];
        g_h1[idx] = state[BATCH * HID + idx];
    }
    if (idx < BATCH) { g_tok[idx] = 1; g_lossacc[idx] = 0.f; g_match[idx] = 1; }
}

__device__ __forceinline__ float fast_tanh(float x) {
    float xc = fminf(fmaxf(x, -9.f), 9.f);
    float e2 = __expf(2.f * xc);
    return __fdividef(e2 - 1.f, e2 + 1.f);
}

// z=0: attention; z=1: finalize(t-1) plane (if do_fin)
__global__ void __launch_bounds__(256) attn_kernel(const float* __restrict__ enc,
                                                   const float* __restrict__ Va,
                                                   const float* __restrict__ bVa,
                                                   float* __restrict__ out_attn,
                                                   const int* __restrict__ target,
                                                   float* __restrict__ out_dec,
                                                   int t, int do_fin) {
    int b = blockIdx.x;
    if (blockIdx.z == 1) {
        if (!do_fin) return;
        finalize_body(target, out_dec, t - 1, b);
        return;
    }
    int warp = threadIdx.x >> 5, lane = threadIdx.x & 31;
    __shared__ float e_sh[SRC];
    __shared__ float w_sh[SRC];

    float part[4] = {0.f, 0.f, 0.f, 0.f};
    for (int h = lane; h < HID; h += 32) {
        const size_t o = (size_t)b * NBIG + h;
        float q = g_CbigP[0][o] + g_CbigP[1][o] + g_CbigP[2][o] + g_CbigP[3][o];
        float va = Va[h];
#pragma unroll
        for (int i = 0; i < 4; ++i) {
            int s = warp * 4 + i;
            part[i] += va * fast_tanh(q + g_kproj[((size_t)s * BATCH + b) * HID + h]);
        }
    }
#pragma unroll
    for (int i = 0; i < 4; ++i) {
#pragma unroll
        for (int o = 16; o > 0; o >>= 1) part[i] += __shfl_xor_sync(0xffffffffu, part[i], o);
        if (lane == 0) e_sh[warp * 4 + i] = part[i] + bVa[0];
    }
    __syncthreads();
    if (threadIdx.x < 32) {
        float x = e_sh[lane], m = x;
#pragma unroll
        for (int o = 16; o > 0; o >>= 1) m = fmaxf(m, __shfl_xor_sync(0xffffffffu, m, o));
        float ex = expf(x - m), s = ex;
#pragma unroll
        for (int o = 16; o > 0; o >>= 1) s += __shfl_xor_sync(0xffffffffu, s, o);
        float w = ex / s;
        w_sh[lane] = w;
        out_attn[((size_t)t * BATCH + b) * SRC + lane] = w;
    }
    __syncthreads();
    for (int h = threadIdx.x; h < HID; h += 256) {
        float c = 0.f;
#pragma unroll
        for (int s = 0; s < SRC; ++s) c += w_sh[s] * enc[((size_t)s * BATCH + b) * HID + h];
        g_ctx[b * HID + h] = c;
    }
}

__device__ __forceinline__ float sigmf(float x) { return 1.f / (1.f + expf(-x)); }

__global__ void gru_pw0() {
    int idx = blockIdx.x * blockDim.x + threadIdx.x;
    int b = idx >> 9, j = idx & 511;
    const size_t o = (size_t)b * G3H;
    float gr = g_giP[0][o + j] + g_giP[1][o + j] + g_giP[2][o + j] + g_giP[3][o + j];
    float gz = g_giP[0][o + HID + j] + g_giP[1][o + HID + j] + g_giP[2][o + HID + j] + g_giP[3][o + HID + j];
    float gn = g_giP[0][o + 2*HID + j] + g_giP[1][o + 2*HID + j] + g_giP[2][o + 2*HID + j] + g_giP[3][o + 2*HID + j];
    float hr = g_ghP[0][o + j] + g_ghP[1][o + j] + g_ghP[2][o + j] + g_ghP[3][o + j];
    float hz = g_ghP[0][o + HID + j] + g_ghP[1][o + HID + j] + g_ghP[2][o + HID + j] + g_ghP[3][o + HID + j];
    float hn = g_ghP[0][o + 2*HID + j] + g_ghP[1][o + 2*HID + j] + g_ghP[2][o + 2*HID + j] + g_ghP[3][o + 2*HID + j];
    float r = sigmf(gr + hr);
    float z = sigmf(gz + hz);
    float n = tanhf(gn + r * hn);
    float hp = g_h0[idx];
    g_h0[idx] = (1.f - z) * n + z * hp;
}

__global__ void gru_pw1() {
    int idx = blockIdx.x * blockDim.x + threadIdx.x;
    int b = idx >> 9, j = idx & 511;
    const size_t o = (size_t)b * G3H;
    const size_t oc = (size_t)b * NBIG + HID;
    float gr = g_giP[0][o + j] + g_giP[1][o + j] + g_giP[2][o + j] + g_giP[3][o + j];
    float gz = g_giP[0][o + HID + j] + g_giP[1][o + HID + j] + g_giP[2][o + HID + j] + g_giP[3][o + HID + j];
    float gn = g_giP[0][o + 2*HID + j] + g_giP[1][o + 2*HID + j] + g_giP[2][o + 2*HID + j] + g_giP[3][o + 2*HID + j];
    float hr = g_CbigP[0][oc + j] + g_CbigP[1][oc + j] + g_CbigP[2][oc + j] + g_CbigP[3][oc + j];
    float hz = g_CbigP[0][oc + HID + j] + g_CbigP[1][oc + HID + j] + g_CbigP[2][oc + HID + j] + g_CbigP[3][oc + HID + j];
    float hn = g_CbigP[0][oc + 2*HID + j] + g_CbigP[1][oc + 2*HID + j] + g_CbigP[2][oc + 2*HID + j] + g_CbigP[3][oc + 2*HID + j];
    float r = sigmf(gr + hr);
    float z = sigmf(gz + hz);
    float n = tanhf(gn + r * hn);
    float hp = g_h1[idx];
    g_h1[idx] = (1.f - z) * n + z * hp;
}

__global__ void __launch_bounds__(256) final_reduce(float* __restrict__ out) {
    __shared__ float sl[256];
    __shared__ int sc[256];
    float l = 0.f; int c = 0;
    for (int b = threadIdx.x; b < BATCH; b += 256) { l += g_lossacc[b]; c += g_match[b]; }
    sl[threadIdx.x] = l; sc[threadIdx.x] = c;
    __syncthreads();
    for (int off = 128; off > 0; off >>= 1) {
        if (threadIdx.x < off) { sl[threadIdx.x] += sl[threadIdx.x + off]; sc[threadIdx.x] += sc[threadIdx.x + off]; }
        __syncthreads();
    }
    if (threadIdx.x == 0) {
        out[OFF_LOSS] = sl[0] / (float)BATCH;
        out[OFF_COR] = (float)sc[0];
    }
}

// ---------------------------------------------------------------- launch
extern "C" void kernel_launch(void* const* d_in, const int* in_sizes, int n_in,
                              void* d_out, int out_size) {
    const float* state = (const float*)d_in[0];
    const float* enc   = (const float*)d_in[1];
    const int*   tgt   = (const int*)d_in[2];
    const float* emb   = (const float*)d_in[3];
    const float* Wa    = (const float*)d_in[4];
    const float* bWa   = (const float*)d_in[5];
    const float* Ua    = (const float*)d_in[6];
    const float* bUa   = (const float*)d_in[7];
    const float* Va    = (const float*)d_in[8];
    const float* bVa   = (const float*)d_in[9];
    const float* W_ih0 = (const float*)d_in[10];
    const float* W_hh0 = (const float*)d_in[11];
    const float* b_ih0 = (const float*)d_in[12];
    const float* b_hh0 = (const float*)d_in[13];
    const float* W_ih1 = (const float*)d_in[14];
    const float* W_hh1 = (const float*)d_in[15];
    const float* b_ih1 = (const float*)d_in[16];
    const float* b_hh1 = (const float*)d_in[17];
    const float* fcW   = (const float*)d_in[18];
    const float* fcb   = (const float*)d_in[19];
    float* out = (float*)d_out;

    // ---- init + weight prep ----
    init_kernel<<<(BATCH * HID + 255) / 256, 256>>>(state);
    wcat_kernel<<<(NBIG * HID + 255) / 256, 256>>>(Wa, W_hh1, bWa, b_hh1, emb);

    // kproj (M=32768, N=512): 1024 blocks
    k_kproj<<<dim3(HID / TN, (SRC * BATCH) / TM), 256>>>(enc, Ua, bUa);
    // EP (M=256, N=1536): 24 blocks
    k_ep<<<dim3(G3H / TN, VOC / TM), 256>>>(W_ih0);

    for (int t = 0; t < TT; ++t) {
        // dual(t) + logits(t-1) plane
        k_dual<<<dim3(NBIG / TN, BATCH / TM, 2 * NSPLIT + 1), 256>>>(
            W_hh0, b_hh0, fcW, fcb, t > 0);
        // attn(t) + finalize(t-1) plane
        attn_kernel<<<dim3(BATCH, 1, 2), 256>>>(enc, Va, bVa, out + OFF_ATT,
                                                tgt, out + OFF_DEC, t, t > 0);
        k_gi0<<<dim3(G3H / TN, BATCH / TM, NSPLIT), 256>>>(W_ih0, b_ih0);
        gru_pw0<<<(BATCH * HID) / 256, 256>>>();
        k_gi1<<<dim3(G3H / TN, BATCH / TM, NSPLIT), 256>>>(W_ih1, b_ih1);
        gru_pw1<<<(BATCH * HID) / 256, 256>>>();
    }

    // tail: logits + finalize for t = TT-1
    k_logits_tail<<<128, 256>>>(fcW, fcb);
    fc_finalize<<<BATCH, 256>>>(tgt, out + OFF_DEC, TT - 1);

    final_reduce<<<1, 256>>>(out);
}